// round 7
// baseline (speedup 1.0000x reference)
#include <cuda_runtime.h>
#include <cuda_bf16.h>
#include <cstdint>
#include <math.h>

#define K_CODES 2048
#define D_DIM   64
#define N_VEC   65536
#define M_TILE  128
#define NTILE   128
#define NT_CNT  (K_CODES / NTILE)     // 16
#define NTHREADS 256
#define NBLOCKS (N_VEC / M_TILE)      // 512

// ---- smem layout (bytes) ----
#define SM_X2    0                    // 128 f
#define SM_IDX   1024                 // 128 i
#define SM_ERR   2048                 // 128 f
#define SM_FLAGC 3072                 // 1 i
#define SM_FLAGS 3088                 // 128 i
#define SM_XROW  4112                 // 64 f
#define SM_A     4608                 // 2 splits x 128 rows x 128B = 32KB
#define SPLIT_A  16384
#define SM_B     (SM_A + 2 * SPLIT_A) // 37376; 2 stages x 2 splits x 16KB
#define SPLIT_B  16384
#define STAGE_B  (2 * SPLIT_B)
#define SMEM_TOTAL (SM_B + 2 * STAGE_B)   // 102912
// post-mainloop scratch overlays B region:
#define SM_RS    SM_B                 // up to 256 f / 128*8 f
#define SM_RI    (SM_B + 4096)
#define SM_RS2   (SM_B + 8192)

__device__ __align__(256) __nv_bfloat16 g_cb0[K_CODES * D_DIM];
__device__ __align__(256) __nv_bfloat16 g_cb1[K_CODES * D_DIM];
__device__ __align__(256) float g_cbT[K_CODES * D_DIM];   // [k][d] fp32
__device__ float    g_cn2[K_CODES];
__device__ int      g_counts[K_CODES];
__device__ float    g_partial[NBLOCKS];
__device__ unsigned g_ticket;

// ---- helpers ----
__device__ __forceinline__ void mma16816(float* d, const uint32_t* a, const uint32_t* b) {
    asm volatile("mma.sync.aligned.m16n8k16.row.col.f32.bf16.bf16.f32 "
                 "{%0,%1,%2,%3}, {%4,%5,%6,%7}, {%8,%9}, {%0,%1,%2,%3};"
                 : "+f"(d[0]), "+f"(d[1]), "+f"(d[2]), "+f"(d[3])
                 : "r"(a[0]), "r"(a[1]), "r"(a[2]), "r"(a[3]), "r"(b[0]), "r"(b[1]));
}
#define CP_ASYNC16(dst, src) \
    asm volatile("cp.async.cg.shared.global [%0], [%1], 16;" :: "r"(dst), "l"(src) : "memory")
#define CP_COMMIT()  asm volatile("cp.async.commit_group;" ::: "memory")
#define CP_WAIT1()   asm volatile("cp.async.wait_group 1;" ::: "memory")
#define CP_WAIT0()   asm volatile("cp.async.wait_group 0;" ::: "memory")

__device__ __forceinline__ uint32_t smem_u32(const void* p) {
    uint32_t a;
    asm("{ .reg .u64 t; cvta.to.shared.u64 t, %1; cvt.u32.u64 %0, t; }" : "=r"(a) : "l"(p));
    return a;
}
__device__ __forceinline__ void split2(float v, uint16_t& s0, uint16_t& s1) {
    __nv_bfloat16 h0 = __float2bfloat16_rn(v);
    __nv_bfloat16 h1 = __float2bfloat16_rn(v - __bfloat162float(h0));
    s0 = __bfloat16_as_ushort(h0);
    s1 = __bfloat16_as_ushort(h1);
}

// ============================ prep kernel ============================
__global__ void vq_prep(const float* __restrict__ cb) {
    int k = blockIdx.x * blockDim.x + threadIdx.x;
    if (k < K_CODES) {
        float s = 0.f;
        #pragma unroll 8
        for (int d = 0; d < D_DIM; d++) {
            float v = cb[(size_t)d * K_CODES + k];
            s = fmaf(v, v, s);
            g_cbT[(size_t)k * D_DIM + d] = v;
            uint16_t a0, a1;
            split2(v, a0, a1);
            g_cb0[(size_t)k * D_DIM + d] = __ushort_as_bfloat16(a0);
            g_cb1[(size_t)k * D_DIM + d] = __ushort_as_bfloat16(a1);
        }
        g_cn2[k] = s;
        g_counts[k] = 0;
    }
    if (k == 0) g_ticket = 0;
}

// ============================ main kernel ============================
__device__ __forceinline__ void load_b_tile(char* smc, int tile, int stage, int tid) {
    const __nv_bfloat16* srcs[2] = { g_cb0, g_cb1 };
    uint32_t base = smem_u32(smc + SM_B + stage * STAGE_B);
    #pragma unroll
    for (int it = 0; it < 8; it++) {                  // 2048 16B chunks / 256 thr
        int v = it * NTHREADS + tid;
        int p = v >> 10;                              // split 0..1
        int r = (v >> 3) & 127;                       // code row in tile
        int c = v & 7;                                // 16B chunk
        const __nv_bfloat16* src = srcs[p] + ((size_t)(tile * NTILE + r)) * D_DIM + c * 8;
        uint32_t dst = base + p * SPLIT_B + r * 128 + ((c ^ (r & 7)) << 4);
        CP_ASYNC16(dst, src);
    }
}

__global__ __launch_bounds__(NTHREADS) void vq_main(
    const float* __restrict__ x, float* __restrict__ out)
{
    extern __shared__ char smc[];
    const int tid = threadIdx.x;
    const int lane = tid & 31, warp = tid >> 5;
    const int mw = warp >> 1, nw = warp & 1;          // 4 M-warps x 2 N-warps
    const int qr = lane >> 2, qc = lane & 3;
    float* x2s   = (float*)(smc + SM_X2);
    int*   sidx  = (int*)(smc + SM_IDX);
    float* serr  = (float*)(smc + SM_ERR);
    int*   flagc = (int*)(smc + SM_FLAGC);
    int*   flags = (int*)(smc + SM_FLAGS);
    float* xrw   = (float*)(smc + SM_XROW);

    if (tid == 0) *flagc = 0;

    // ---- convert 128-row x tile into 2 bf16 splits (swizzled rows); 2 thr/row ----
    {
        const int m = tid >> 1;
        const int half = tid & 1;
        const float* xrow = x + ((size_t)blockIdx.x * M_TILE + m) * D_DIM + half * 32;
        float x2p = 0.f;
        #pragma unroll
        for (int jj = 0; jj < 4; jj++) {              // 4 chunks of 8 floats
            float4 va = __ldg((const float4*)xrow + jj * 2);
            float4 vb = __ldg((const float4*)xrow + jj * 2 + 1);
            float f[8] = { va.x, va.y, va.z, va.w, vb.x, vb.y, vb.z, vb.w };
            uint16_t s0[8], s1[8];
            #pragma unroll
            for (int e = 0; e < 8; e++) {
                x2p = fmaf(f[e], f[e], x2p);
                split2(f[e], s0[e], s1[e]);
            }
            int j = half * 4 + jj;                    // global chunk 0..7
            uint32_t off = m * 128 + ((j ^ (m & 7)) << 4);
            uint4 w0, w1;
            w0.x = (uint32_t)s0[1] << 16 | s0[0];  w0.y = (uint32_t)s0[3] << 16 | s0[2];
            w0.z = (uint32_t)s0[5] << 16 | s0[4];  w0.w = (uint32_t)s0[7] << 16 | s0[6];
            w1.x = (uint32_t)s1[1] << 16 | s1[0];  w1.y = (uint32_t)s1[3] << 16 | s1[2];
            w1.z = (uint32_t)s1[5] << 16 | s1[4];  w1.w = (uint32_t)s1[7] << 16 | s1[6];
            *(uint4*)(smc + SM_A + off) = w0;
            *(uint4*)(smc + SM_A + SPLIT_A + off) = w1;
        }
        float x2f = x2p + __shfl_xor_sync(0xffffffffu, x2p, 1);
        if (half == 0) x2s[m] = x2f;
    }
    __syncthreads();

    // ---- fragment address bases (swizzle value = qr for both A and B) ----
    const int kb = qc * 4;
    uint32_t cs[8];
    #pragma unroll
    for (int c = 0; c < 8; c++) cs[c] = (uint32_t)((c ^ qr) << 4);
    uint32_t rowA[2];
    #pragma unroll
    for (int mt = 0; mt < 2; mt++)
        rowA[mt] = (uint32_t)((mw * 32 + mt * 16 + qr) * 128 + kb);
    uint32_t rowB[8];
    #pragma unroll
    for (int nt = 0; nt < 8; nt++)
        rowB[nt] = (uint32_t)((nw * 64 + nt * 8 + qr) * 128 + kb);

    const int pa[3] = { 1, 0, 0 };                    // small terms first
    const int pb[3] = { 0, 1, 0 };

    float b1[4], b2[4];
    int   i1[4];
    #pragma unroll
    for (int i = 0; i < 4; i++) { b1[i] = 3.4e38f; b2[i] = 3.4e38f; i1[i] = 0; }

    load_b_tile(smc, 0, 0, tid); CP_COMMIT();

    for (int t = 0; t < NT_CNT; t++) {
        const int st = t & 1;
        if (t + 1 < NT_CNT) { load_b_tile(smc, t + 1, 1 - st, tid); CP_COMMIT(); CP_WAIT1(); }
        else                { CP_WAIT0(); }
        __syncthreads();

        float acc[2][8][4];
        #pragma unroll
        for (int mt = 0; mt < 2; mt++)
            #pragma unroll
            for (int nt = 0; nt < 8; nt++)
                #pragma unroll
                for (int e = 0; e < 4; e++) acc[mt][nt][e] = 0.f;

        const char* Bst = smc + SM_B + st * STAGE_B;
        #pragma unroll
        for (int p = 0; p < 3; p++) {
            const char* Ab = smc + SM_A + pa[p] * SPLIT_A;
            const char* Bb = Bst + pb[p] * SPLIT_B;
            #pragma unroll
            for (int k4 = 0; k4 < 4; k4++) {
                const uint32_t ca = cs[k4 * 2], cb = cs[k4 * 2 + 1];
                uint32_t bf[8][2];
                #pragma unroll
                for (int nt = 0; nt < 8; nt++) {
                    bf[nt][0] = *(const uint32_t*)(Bb + rowB[nt] + ca);
                    bf[nt][1] = *(const uint32_t*)(Bb + rowB[nt] + cb);
                }
                #pragma unroll
                for (int mt = 0; mt < 2; mt++) {
                    uint32_t af[4];
                    af[0] = *(const uint32_t*)(Ab + rowA[mt] + ca);
                    af[1] = *(const uint32_t*)(Ab + rowA[mt] + 1024 + ca);
                    af[2] = *(const uint32_t*)(Ab + rowA[mt] + cb);
                    af[3] = *(const uint32_t*)(Ab + rowA[mt] + 1024 + cb);
                    #pragma unroll
                    for (int nt = 0; nt < 8; nt++)
                        mma16816(acc[mt][nt], af, bf[nt]);
                }
            }
        }

        // ---- epilogue: scores + running (best, second-best) ----
        #pragma unroll
        for (int nt = 0; nt < 8; nt++) {
            const int n0 = t * NTILE + nw * 64 + nt * 8 + qc * 2;
            const float2 c2 = __ldg((const float2*)(g_cn2 + n0));
            #pragma unroll
            for (int mt = 0; mt < 2; mt++) {
                #pragma unroll
                for (int h = 0; h < 2; h++) {
                    const int sl = mt * 2 + h;
                    float s0 = fmaf(-2.f, acc[mt][nt][h * 2 + 0], c2.x);
                    float s1 = fmaf(-2.f, acc[mt][nt][h * 2 + 1], c2.y);
                    if (s0 < b1[sl]) { b2[sl] = b1[sl]; b1[sl] = s0; i1[sl] = n0; }
                    else if (s0 < b2[sl]) b2[sl] = s0;
                    if (s1 < b1[sl]) { b2[sl] = b1[sl]; b1[sl] = s1; i1[sl] = n0 + 1; }
                    else if (s1 < b2[sl]) b2[sl] = s1;
                }
            }
        }
        __syncthreads();
    }

    // ---- cross-thread merge: 8 contributors per row ----
    float* rs  = (float*)(smc + SM_RS);
    int*   ri  = (int*)(smc + SM_RI);
    float* rs2 = (float*)(smc + SM_RS2);
    const int cid = nw * 4 + qc;
    #pragma unroll
    for (int mt = 0; mt < 2; mt++)
        #pragma unroll
        for (int h = 0; h < 2; h++) {
            int m = mw * 32 + mt * 16 + qr + h * 8;
            rs[m * 8 + cid]  = b1[mt * 2 + h];
            ri[m * 8 + cid]  = i1[mt * 2 + h];
            rs2[m * 8 + cid] = b2[mt * 2 + h];
        }
    __syncthreads();

    if (tid < M_TILE) {
        float B1 = rs[tid * 8];  int I1 = ri[tid * 8];  float B2 = rs2[tid * 8];
        #pragma unroll
        for (int c = 1; c < 8; c++) {
            float b = rs[tid * 8 + c];
            int   i = ri[tid * 8 + c];
            float bb = rs2[tid * 8 + c];
            if (b < B1 || (b == B1 && i < I1)) { B2 = fminf(B1, bb); B1 = b; I1 = i; }
            else B2 = fminf(B2, fminf(b, bb));
        }
        sidx[tid] = I1;
        serr[tid] = x2s[tid] + B1;
        float eps = 2e-4f * sqrtf(x2s[tid]) + 1e-5f;   // rigorous 2-way-split bound
        if (B2 - B1 < eps) {
            int fp = atomicAdd(flagc, 1);
            flags[fp] = tid;
        }
    }
    __syncthreads();

    // ---- exact fp32 re-check for flagged rows (rare) ----
    const int nf = *flagc;
    for (int f = 0; f < nf; f++) {
        const int r = flags[f];
        if (tid < 16)
            ((float4*)xrw)[tid] = __ldg((const float4*)(x + ((size_t)blockIdx.x * M_TILE + r) * D_DIM) + tid);
        __syncthreads();
        float lmin = 3.4e38f;
        int   lidx = 0;
        #pragma unroll
        for (int j = 0; j < 8; j++) {
            int k = tid * 8 + j;
            const float* cr = g_cbT + (size_t)k * D_DIM;
            float dot = 0.f;
            #pragma unroll 16
            for (int d = 0; d < D_DIM; d++) dot = fmaf(xrw[d], __ldg(cr + d), dot);
            float s = g_cn2[k] - 2.f * dot;
            if (s < lmin) { lmin = s; lidx = k; }
        }
        rs[tid] = lmin; ri[tid] = lidx;
        __syncthreads();
        for (int s = 128; s > 0; s >>= 1) {
            if (tid < s) {
                float o = rs[tid + s]; int oi = ri[tid + s];
                if (o < rs[tid] || (o == rs[tid] && oi < ri[tid])) { rs[tid] = o; ri[tid] = oi; }
            }
            __syncthreads();
        }
        if (tid == 0) { sidx[r] = ri[0]; serr[r] = x2s[r] + rs[0]; }
        __syncthreads();
    }

    // ---- histogram, gather, error reduction ----
    if (tid < M_TILE) atomicAdd(&g_counts[sidx[tid]], 1);
    __syncthreads();

    #pragma unroll
    for (int it = 0; it < 8; it++) {
        int idx4 = it * NTHREADS + tid;               // 2048 float4s
        int n = idx4 >> 4, d4 = idx4 & 15;
        float4 v = __ldg((const float4*)(g_cbT + (size_t)sidx[n] * D_DIM) + d4);
        ((float4*)(out + ((size_t)blockIdx.x * M_TILE + n) * D_DIM))[d4] = v;
    }

    rs[tid] = (tid < M_TILE) ? serr[tid] : 0.f;
    __syncthreads();
    for (int s = 128; s > 0; s >>= 1) {
        if (tid < s) rs[tid] += rs[tid + s];
        __syncthreads();
    }
    if (tid == 0) g_partial[blockIdx.x] = rs[0];

    // ---- last block: finalize scalars, reset for replay ----
    __shared__ int s_last;
    __threadfence();
    if (tid == 0) s_last = (atomicAdd(&g_ticket, 1u) == NBLOCKS - 1);
    __syncthreads();
    if (!s_last) return;
    __threadfence();

    rs[tid] = g_partial[tid] + g_partial[tid + 256];  // NBLOCKS = 512
    __syncthreads();
    for (int s = 128; s > 0; s >>= 1) {
        if (tid < s) rs[tid] += rs[tid + s];
        __syncthreads();
    }
    float mse = rs[0] / (float)((size_t)N_VEC * D_DIM);
    __syncthreads();

    const float invN = 1.f / (float)N_VEC;
    float e = 0.f;
    for (int j = tid; j < K_CODES; j += NTHREADS) {
        float pr = (float)g_counts[j] * invN;
        e += pr * logf(pr + 1e-10f);
    }
    rs[tid] = e;
    __syncthreads();
    for (int s = 128; s > 0; s >>= 1) {
        if (tid < s) rs[tid] += rs[tid + s];
        __syncthreads();
    }
    if (tid == 0) {
        out[(size_t)N_VEC * D_DIM + 0] = expf(-rs[0]);   // perplexity
        out[(size_t)N_VEC * D_DIM + 1] = mse;            // codebook_loss
        out[(size_t)N_VEC * D_DIM + 2] = 0.25f * mse;    // commitment_loss
    }
    __syncthreads();
    for (int j = tid; j < K_CODES; j += NTHREADS) g_counts[j] = 0;
    if (tid == 0) g_ticket = 0;
}

// ============================ launcher ============================
extern "C" void kernel_launch(void* const* d_in, const int* in_sizes, int n_in,
                              void* d_out, int out_size) {
    const float* a = (const float*)d_in[0];
    const float* b = (const float*)d_in[1];
    const float* x  = a;
    const float* cb = b;
    if (n_in >= 2 && in_sizes[0] < in_sizes[1]) { x = b; cb = a; }
    float* out = (float*)d_out;

    cudaFuncSetAttribute(vq_main, cudaFuncAttributeMaxDynamicSharedMemorySize, SMEM_TOTAL);

    vq_prep<<<K_CODES / 256, 256>>>(cb);
    vq_main<<<NBLOCKS, NTHREADS, SMEM_TOTAL>>>(x, out);
}

// round 8
// speedup vs baseline: 3.2745x; 3.2745x over previous
#include <cuda_runtime.h>
#include <cuda_bf16.h>
#include <cstdint>
#include <math.h>

#define K_CODES 2048
#define D_DIM   64
#define N_VEC   65536
#define M_TILE  128
#define NTILE   128
#define NT_CNT  (K_CODES / NTILE)     // 16
#define NTHREADS 256
#define NBLOCKS (N_VEC / M_TILE)      // 512

// ---- smem layout (bytes) ----
#define SM_X2    0
#define SM_IDX   1024
#define SM_ERR   2048
#define SM_FLAGC 3072
#define SM_FLAGS 3088
#define SM_XROW  4112
#define SM_A     4608
#define SPLIT_A  16384                // 128 rows x 64 k x 2B, frag order
#define SM_B     (SM_A + 2 * SPLIT_A) // 37376
#define SPLIT_B  16384                // 128 codes x 64 k x 2B, frag order
#define STAGE_B  (2 * SPLIT_B)
#define SMEM_TOTAL (SM_B + 2 * STAGE_B)   // 102912
// post-mainloop overlays in B region:
#define SM_RS    SM_B
#define SM_RI    (SM_B + 4096)
#define SM_RS2   (SM_B + 8192)
#define SM_RI2   (SM_B + 12288)

__device__ __align__(256) uint4 g_cbF[2][16384];          // [split][tile*1024 + (kb*8+p)*32 + lane]
__device__ __align__(256) float g_cbT[K_CODES * D_DIM];   // [k][d] fp32
__device__ float    g_cn2[K_CODES];
__device__ int      g_counts[K_CODES];
__device__ float    g_partial[NBLOCKS];
__device__ unsigned g_ticket;

// ---- helpers ----
__device__ __forceinline__ void mma16816(float* d, const uint32_t* a, const uint32_t* b) {
    asm volatile("mma.sync.aligned.m16n8k16.row.col.f32.bf16.bf16.f32 "
                 "{%0,%1,%2,%3}, {%4,%5,%6,%7}, {%8,%9}, {%0,%1,%2,%3};"
                 : "+f"(d[0]), "+f"(d[1]), "+f"(d[2]), "+f"(d[3])
                 : "r"(a[0]), "r"(a[1]), "r"(a[2]), "r"(a[3]), "r"(b[0]), "r"(b[1]));
}
#define CP_ASYNC16(dst, src) \
    asm volatile("cp.async.cg.shared.global [%0], [%1], 16;" :: "r"(dst), "l"(src) : "memory")
#define CP_COMMIT()  asm volatile("cp.async.commit_group;" ::: "memory")
#define CP_WAIT1()   asm volatile("cp.async.wait_group 1;" ::: "memory")
#define CP_WAIT0()   asm volatile("cp.async.wait_group 0;" ::: "memory")

__device__ __forceinline__ uint32_t smem_u32(const void* p) {
    uint32_t a;
    asm("{ .reg .u64 t; cvta.to.shared.u64 t, %1; cvt.u32.u64 %0, t; }" : "=r"(a) : "l"(p));
    return a;
}
__device__ __forceinline__ void split2(float v, uint16_t& s0, uint16_t& s1) {
    __nv_bfloat16 h0 = __float2bfloat16_rn(v);
    __nv_bfloat16 h1 = __float2bfloat16_rn(v - __bfloat162float(h0));
    s0 = __bfloat16_as_ushort(h0);
    s1 = __bfloat16_as_ushort(h1);
}

// ============================ prep kernels ============================
__global__ void vq_prep1(const float* __restrict__ cb) {
    int k = blockIdx.x * blockDim.x + threadIdx.x;
    if (k < K_CODES) {
        float s = 0.f;
        #pragma unroll 8
        for (int d = 0; d < D_DIM; d++) {
            float v = cb[(size_t)d * K_CODES + k];
            s = fmaf(v, v, s);
            g_cbT[(size_t)k * D_DIM + d] = v;
        }
        g_cn2[k] = s;
        g_counts[k] = 0;
    }
    if (k == 0) g_ticket = 0;
}

// frag-order, pair-interleaved B splits (mapping verified in R5 run)
__global__ void vq_prep2(const float* __restrict__ cb) {
    int gid = blockIdx.x * blockDim.x + threadIdx.x;   // 16384
    int lane = gid & 31, p = (gid >> 5) & 7, kb = (gid >> 8) & 3, tile = gid >> 10;
    int n_e = tile * NTILE + (2 * p) * 8 + (lane >> 2);
    int n_o = n_e + 8;
    int k0  = kb * 16 + (lane & 3) * 2;

    float ve0 = cb[(size_t)(k0    ) * K_CODES + n_e];
    float ve1 = cb[(size_t)(k0 + 1) * K_CODES + n_e];
    float ve8 = cb[(size_t)(k0 + 8) * K_CODES + n_e];
    float ve9 = cb[(size_t)(k0 + 9) * K_CODES + n_e];
    float vo0 = cb[(size_t)(k0    ) * K_CODES + n_o];
    float vo1 = cb[(size_t)(k0 + 1) * K_CODES + n_o];
    float vo8 = cb[(size_t)(k0 + 8) * K_CODES + n_o];
    float vo9 = cb[(size_t)(k0 + 9) * K_CODES + n_o];

    uint16_t a[8], b[8];
    split2(ve0, a[0], b[0]); split2(ve1, a[1], b[1]);
    split2(ve8, a[2], b[2]); split2(ve9, a[3], b[3]);
    split2(vo0, a[4], b[4]); split2(vo1, a[5], b[5]);
    split2(vo8, a[6], b[6]); split2(vo9, a[7], b[7]);

    int off = tile * 1024 + (kb * 8 + p) * 32 + lane;
    g_cbF[0][off] = make_uint4((uint32_t)a[1] << 16 | a[0], (uint32_t)a[3] << 16 | a[2],
                               (uint32_t)a[5] << 16 | a[4], (uint32_t)a[7] << 16 | a[6]);
    g_cbF[1][off] = make_uint4((uint32_t)b[1] << 16 | b[0], (uint32_t)b[3] << 16 | b[2],
                               (uint32_t)b[5] << 16 | b[4], (uint32_t)b[7] << 16 | b[6]);
}

// ============================ main kernel ============================
__device__ __forceinline__ void load_b_tile(char* smc, int tile, int stage, int tid) {
    uint32_t base = smem_u32(smc + SM_B + stage * STAGE_B);
    #pragma unroll
    for (int it = 0; it < 8; it++) {                  // 2048 16B chunks / 256 thr
        int v = it * NTHREADS + tid;
        int sp = v >> 10;
        int c  = v & 1023;
        const char* src = (const char*)(g_cbF[sp] + tile * 1024 + c);
        CP_ASYNC16(base + sp * SPLIT_B + c * 16, src);
    }
}

__global__ __launch_bounds__(NTHREADS) void vq_main(
    const float* __restrict__ x, float* __restrict__ out)
{
    extern __shared__ char smc[];
    const int tid = threadIdx.x;
    const int lane = tid & 31, warp = tid >> 5;
    const int mw = warp >> 1, nw = warp & 1;          // 4 M-warps x 2 N-warps
    const int qr = lane >> 2, qc = lane & 3;
    float* x2s   = (float*)(smc + SM_X2);
    int*   sidx  = (int*)(smc + SM_IDX);
    float* serr  = (float*)(smc + SM_ERR);
    int*   flagc = (int*)(smc + SM_FLAGC);
    int*   flags = (int*)(smc + SM_FLAGS);
    float* xrw   = (float*)(smc + SM_XROW);

    if (tid == 0) *flagc = 0;

    // ---- convert 128-row x tile into 2 bf16 splits in A-frag order; 2 thr/row ----
    {
        const int m = tid >> 1;
        const int half = tid & 1;
        const float* xrow = x + ((size_t)blockIdx.x * M_TILE + m) * D_DIM + half * 32;
        float x2p = 0.f;
        #pragma unroll
        for (int jj = 0; jj < 4; jj++) {
            float4 va = __ldg((const float4*)xrow + jj * 2);
            float4 vb = __ldg((const float4*)xrow + jj * 2 + 1);
            float f[8] = { va.x, va.y, va.z, va.w, vb.x, vb.y, vb.z, vb.w };
            #pragma unroll
            for (int e = 0; e < 4; e++) {
                float f0 = f[e * 2], f1 = f[e * 2 + 1];
                x2p = fmaf(f0, f0, x2p);
                x2p = fmaf(f1, f1, x2p);
                int d = half * 32 + jj * 8 + e * 2;
                uint16_t p0, q0, p1, q1;
                split2(f0, p0, q0);
                split2(f1, p1, q1);
                int lane_f = ((m & 7) << 2) | ((d >> 1) & 3);
                int a_slot = ((m >> 3) & 1) | (((d >> 3) & 1) << 1);
                int off = (((m >> 4) * 4 + (d >> 4)) * 32 + lane_f) * 16 + a_slot * 4;
                *(uint32_t*)(smc + SM_A + off) = (uint32_t)p1 << 16 | p0;
                *(uint32_t*)(smc + SM_A + SPLIT_A + off) = (uint32_t)q1 << 16 | q0;
            }
        }
        float x2f = x2p + __shfl_xor_sync(0xffffffffu, x2p, 1);
        if (half == 0) x2s[m] = x2f;
    }
    __syncthreads();

    const uint32_t laneoff = lane * 16;
    const int pa[3] = { 1, 0, 0 };                    // small terms first
    const int pb[3] = { 0, 1, 0 };

    float b1[4], b2[4];
    int   i1[4], i2[4];
    #pragma unroll
    for (int i = 0; i < 4; i++) { b1[i] = 3.4e38f; b2[i] = 3.4e38f; i1[i] = 0; i2[i] = 1; }

    load_b_tile(smc, 0, 0, tid); CP_COMMIT();

    for (int t = 0; t < NT_CNT; t++) {
        const int st = t & 1;
        if (t + 1 < NT_CNT) { load_b_tile(smc, t + 1, 1 - st, tid); CP_COMMIT(); CP_WAIT1(); }
        else                { CP_WAIT0(); }
        __syncthreads();

        float acc[2][8][4];
        #pragma unroll
        for (int mt = 0; mt < 2; mt++)
            #pragma unroll
            for (int nt = 0; nt < 8; nt++)
                #pragma unroll
                for (int e = 0; e < 4; e++) acc[mt][nt][e] = 0.f;

        #pragma unroll
        for (int p = 0; p < 3; p++) {
            const char* Ab = smc + SM_A + pa[p] * SPLIT_A;
            const char* Bb = smc + SM_B + st * STAGE_B + pb[p] * SPLIT_B;
            #pragma unroll
            for (int kb = 0; kb < 4; kb++) {
                uint4 bq[4];
                #pragma unroll
                for (int g2 = 0; g2 < 4; g2++)
                    bq[g2] = *(const uint4*)(Bb + (kb * 8 + nw * 4 + g2) * 512 + laneoff);
                #pragma unroll
                for (int mt = 0; mt < 2; mt++) {
                    uint4 aq = *(const uint4*)(Ab + ((mw * 2 + mt) * 4 + kb) * 512 + laneoff);
                    const uint32_t a[4] = { aq.x, aq.y, aq.z, aq.w };
                    #pragma unroll
                    for (int g2 = 0; g2 < 4; g2++) {
                        const uint32_t be[2] = { bq[g2].x, bq[g2].y };
                        const uint32_t bo[2] = { bq[g2].z, bq[g2].w };
                        mma16816(acc[mt][2 * g2],     a, be);
                        mma16816(acc[mt][2 * g2 + 1], a, bo);
                    }
                }
            }
        }

        // ---- branchless epilogue: top-2 with indices ----
        #pragma unroll
        for (int nt = 0; nt < 8; nt++) {
            const int n0 = t * NTILE + nw * 64 + nt * 8 + qc * 2;
            const float2 c2 = __ldg((const float2*)(g_cn2 + n0));
            #pragma unroll
            for (int mt = 0; mt < 2; mt++) {
                #pragma unroll
                for (int h = 0; h < 2; h++) {
                    const int sl = mt * 2 + h;
                    #pragma unroll
                    for (int e = 0; e < 2; e++) {
                        float s = fmaf(-2.f, acc[mt][nt][h * 2 + e], e ? c2.y : c2.x);
                        int   n = n0 + e;
                        bool lt1 = s < b1[sl];
                        bool lt2 = s < b2[sl];
                        float cand = fmaxf(s, b1[sl]);        // displaced-or-self
                        int   candi = lt1 ? i1[sl] : n;
                        b2[sl] = fminf(b2[sl], cand);
                        i2[sl] = lt2 ? candi : i2[sl];
                        b1[sl] = fminf(b1[sl], s);
                        i1[sl] = lt1 ? n : i1[sl];
                    }
                }
            }
        }
        __syncthreads();
    }

    // ---- cross-thread merge (8 contributors per row) ----
    float* rs  = (float*)(smc + SM_RS);
    int*   ri  = (int*)(smc + SM_RI);
    float* rs2 = (float*)(smc + SM_RS2);
    int*   ri2 = (int*)(smc + SM_RI2);
    const int cid = nw * 4 + qc;
    #pragma unroll
    for (int mt = 0; mt < 2; mt++)
        #pragma unroll
        for (int h = 0; h < 2; h++) {
            int m = mw * 32 + mt * 16 + qr + h * 8;
            rs [m * 8 + cid] = b1[mt * 2 + h];
            ri [m * 8 + cid] = i1[mt * 2 + h];
            rs2[m * 8 + cid] = b2[mt * 2 + h];
            ri2[m * 8 + cid] = i2[mt * 2 + h];
        }
    __syncthreads();

    if (tid < M_TILE) {
        float B1 = 3.4e38f, B2 = 3.4e38f, B3 = 3.4e38f;
        int   I1 = 0, I2 = 0;
        #pragma unroll
        for (int c = 0; c < 8; c++) {
            #pragma unroll
            for (int w = 0; w < 2; w++) {
                float v  = w ? rs2[tid * 8 + c] : rs[tid * 8 + c];
                int   vi = w ? ri2[tid * 8 + c] : ri[tid * 8 + c];
                if (v < B1 || (v == B1 && vi < I1)) { B3 = B2; B2 = B1; I2 = I1; B1 = v; I1 = vi; }
                else if (v < B2 || (v == B2 && vi < I2)) { B3 = B2; B2 = v; I2 = vi; }
                else if (v < B3) B3 = v;
            }
        }
        float x2 = x2s[tid];
        sidx[tid] = I1;
        serr[tid] = x2 + B1;
        float eps = 4e-5f * sqrtf(x2) + 5e-6f;
        if (B2 - B1 < eps) {
            // exact fp32 compare of the two candidates (parallel, no syncs)
            const float* xr  = x + ((size_t)blockIdx.x * M_TILE + tid) * D_DIM;
            const float* c1p = g_cbT + (size_t)I1 * D_DIM;
            const float* c2p = g_cbT + (size_t)I2 * D_DIM;
            float d1 = 0.f, d2 = 0.f;
            #pragma unroll 16
            for (int d = 0; d < D_DIM; d++) {
                float xv = __ldg(xr + d);
                d1 = fmaf(xv, __ldg(c1p + d), d1);
                d2 = fmaf(xv, __ldg(c2p + d), d2);
            }
            float s1 = fmaf(-2.f, d1, g_cn2[I1]);
            float s2 = fmaf(-2.f, d2, g_cn2[I2]);
            if (s2 < s1 || (s2 == s1 && I2 < I1)) { sidx[tid] = I2; serr[tid] = x2 + s2; }
            else serr[tid] = x2 + s1;
            if (B3 - B1 < eps) {                      // 3rd candidate too close: full scan
                int fp = atomicAdd(flagc, 1);
                flags[fp] = tid;
            }
        }
    }
    __syncthreads();

    // ---- rare full-scan fallback ----
    const int nf = *flagc;
    for (int f = 0; f < nf; f++) {
        const int r = flags[f];
        if (tid < 16)
            ((float4*)xrw)[tid] = __ldg((const float4*)(x + ((size_t)blockIdx.x * M_TILE + r) * D_DIM) + tid);
        __syncthreads();
        float lmin = 3.4e38f;
        int   lidx = 0;
        #pragma unroll
        for (int j = 0; j < 8; j++) {
            int k = tid * 8 + j;
            const float* cr = g_cbT + (size_t)k * D_DIM;
            float dot = 0.f;
            #pragma unroll 16
            for (int d = 0; d < D_DIM; d++) dot = fmaf(xrw[d], __ldg(cr + d), dot);
            float s = fmaf(-2.f, dot, g_cn2[k]);
            if (s < lmin) { lmin = s; lidx = k; }
        }
        rs[tid] = lmin; ri[tid] = lidx;
        __syncthreads();
        for (int s = 128; s > 0; s >>= 1) {
            if (tid < s) {
                float o = rs[tid + s]; int oi = ri[tid + s];
                if (o < rs[tid] || (o == rs[tid] && oi < ri[tid])) { rs[tid] = o; ri[tid] = oi; }
            }
            __syncthreads();
        }
        if (tid == 0) { sidx[r] = ri[0]; serr[r] = x2s[r] + rs[0]; }
        __syncthreads();
    }

    // ---- histogram, gather, error reduction ----
    if (tid < M_TILE) atomicAdd(&g_counts[sidx[tid]], 1);
    __syncthreads();

    #pragma unroll
    for (int it = 0; it < 8; it++) {
        int idx4 = it * NTHREADS + tid;               // 2048 float4s
        int n = idx4 >> 4, d4 = idx4 & 15;
        float4 v = __ldg((const float4*)(g_cbT + (size_t)sidx[n] * D_DIM) + d4);
        ((float4*)(out + ((size_t)blockIdx.x * M_TILE + n) * D_DIM))[d4] = v;
    }

    rs[tid] = (tid < M_TILE) ? serr[tid] : 0.f;
    __syncthreads();
    for (int s = 128; s > 0; s >>= 1) {
        if (tid < s) rs[tid] += rs[tid + s];
        __syncthreads();
    }
    if (tid == 0) g_partial[blockIdx.x] = rs[0];

    // ---- last block: finalize scalars, reset for replay ----
    __shared__ int s_last;
    __threadfence();
    if (tid == 0) s_last = (atomicAdd(&g_ticket, 1u) == NBLOCKS - 1);
    __syncthreads();
    if (!s_last) return;
    __threadfence();

    rs[tid] = g_partial[tid] + g_partial[tid + 256];  // NBLOCKS = 512
    __syncthreads();
    for (int s = 128; s > 0; s >>= 1) {
        if (tid < s) rs[tid] += rs[tid + s];
        __syncthreads();
    }
    float mse = rs[0] / (float)((size_t)N_VEC * D_DIM);
    __syncthreads();

    const float invN = 1.f / (float)N_VEC;
    float e = 0.f;
    for (int j = tid; j < K_CODES; j += NTHREADS) {
        float pr = (float)g_counts[j] * invN;
        e += pr * logf(pr + 1e-10f);
    }
    rs[tid] = e;
    __syncthreads();
    for (int s = 128; s > 0; s >>= 1) {
        if (tid < s) rs[tid] += rs[tid + s];
        __syncthreads();
    }
    if (tid == 0) {
        out[(size_t)N_VEC * D_DIM + 0] = expf(-rs[0]);   // perplexity
        out[(size_t)N_VEC * D_DIM + 1] = mse;            // codebook_loss
        out[(size_t)N_VEC * D_DIM + 2] = 0.25f * mse;    // commitment_loss
    }
    __syncthreads();
    for (int j = tid; j < K_CODES; j += NTHREADS) g_counts[j] = 0;
    if (tid == 0) g_ticket = 0;
}

// ============================ launcher ============================
extern "C" void kernel_launch(void* const* d_in, const int* in_sizes, int n_in,
                              void* d_out, int out_size) {
    const float* a = (const float*)d_in[0];
    const float* b = (const float*)d_in[1];
    const float* x  = a;
    const float* cb = b;
    if (n_in >= 2 && in_sizes[0] < in_sizes[1]) { x = b; cb = a; }
    float* out = (float*)d_out;

    cudaFuncSetAttribute(vq_main, cudaFuncAttributeMaxDynamicSharedMemorySize, SMEM_TOTAL);

    vq_prep1<<<K_CODES / 256, 256>>>(cb);
    vq_prep2<<<64, 256>>>(cb);
    vq_main<<<NBLOCKS, NTHREADS, SMEM_TOTAL>>>(x, out);
}